// round 15
// baseline (speedup 1.0000x reference)
#include <cuda_runtime.h>
#include <math.h>

#define NLOC 196
#define NPART 128
#define NBLK 148
#define PI_F 3.14159265358979323846f
#define FPSCALE 1048576.0f          // 2^20
#define INV_FPSCALE (1.0f/1048576.0f)

// Globals (allocation-free rule). All slots plain-written by owners; barrier
// counters are MONOTONIC tickets => no reset needed across graph replays.
__device__ unsigned long long g_part[NPART][NLOC];  // (sum<<32 | sumsq), both *2^20, per 4-batch slice
__device__ float2 g_stats[NLOC];                    // (mean, pi/(sd+1e-8))
__device__ float4 g_W[81];                          // z = W * (v01 x v23)
__device__ unsigned long long g_bar[2];             // monotonic grid-barrier tickets

__device__ __forceinline__ void grid_barrier(int which) {
    __syncthreads();
    if (threadIdx.x == 0) {
        __threadfence();
        unsigned long long t = atomicAdd(&g_bar[which], 1ULL) + 1ULL;
        unsigned long long target = ((t + (NBLK - 1)) / NBLK) * NBLK;
        while (atomicAdd(&g_bar[which], 0ULL) < target) __nanosleep(64);
        __threadfence();
    }
    __syncthreads();
}

// spread bits of 4-bit x: bit i -> bit 2i
__device__ __forceinline__ int spread4(int x) {
    return (x & 1) | ((x & 2) << 1) | ((x & 4) << 2) | ((x & 8) << 3);
}

// One wire contraction of the pair-tensor (see R12/R13)
#define CSTEP(IN, OUT, NB, NM)                                         \
  do {                                                                 \
    const int cnt = (NB) * 3 * (NM);                                   \
    for (int e = tid; e < 4 * cnt; e += 256) {                         \
      int i = e / cnt; int o = e - i * cnt;                            \
      int M = o % (NM); int rest = o / (NM);                           \
      int m = rest % 3; int B = rest / 3;                              \
      float x0 = IN[i][(B * 4 + 0) * (NM) + M];                        \
      float x1 = IN[i][(B * 4 + 1) * (NM) + M];                        \
      float x2 = IN[i][(B * 4 + 2) * (NM) + M];                        \
      float x3 = IN[i][(B * 4 + 3) * (NM) + M];                        \
      float rV;                                                        \
      if (m == 0)      rV = 0.5f * (x0 + x3);                          \
      else if (m == 1) rV = 0.5f * (x0 - x3);                          \
      else             rV = 0.5f * (x1 + x2);                          \
      OUT[i][o] = rV;                                                  \
    }                                                                  \
    __syncthreads();                                                   \
  } while (0)

// ---------------------------------------------------------------------------
// Persistent kernel: 148 blocks x 256 threads (1/SM => co-resident, spin-safe).
//   A: blocks 0-127 stats partials (4 batches each); block 128 builds W.
//   B: warps 0-195 reduce 128 partials -> g_stats (int64, fixed order).
//   C: blocks 0-127 stage 4 batches + eval (R13 plain-FMA body).
// Wire j <-> bit (3-j) of state index K.
// ---------------------------------------------------------------------------
__global__ void __launch_bounds__(256, 1) qf_persistent(const float* __restrict__ x,
                                                        const float* __restrict__ params,
                                                        float* __restrict__ out) {
    __shared__ unsigned long long accP[NLOC];
    __shared__ float sP[16 * 17], sQ[16 * 17];
    __shared__ float bufA[4][256], bufB[4][256];
    __shared__ float sx[4 * 784];
    __shared__ float4 sWk[81];
    __shared__ float2 sStats[NLOC];

    const int tid = threadIdx.x;
    const int bid = blockIdx.x;

    // ================= Phase A =================
    if (bid < NPART) {
        for (int e = tid; e < NLOC; e += 256) accP[e] = 0ULL;
        __syncthreads();

        // 4 batches = 784 float4, all coalesced
        const float4* xs = reinterpret_cast<const float4*>(x) + bid * 784;
        for (int i = tid; i < 784; i += 256) {
            float4 v = xs[i];
            int idx4 = i % 196;
            int off  = idx4 * 4;
            int row  = off / 28;
            int cq   = off - row * 28;
            int loc  = (row >> 1) * 14 + (cq >> 1);
            long long s0 = __float2ll_rn((v.x + v.y) * FPSCALE);
            long long q0 = __float2ll_rn((v.x * v.x + v.y * v.y) * FPSCALE);
            long long s1 = __float2ll_rn((v.z + v.w) * FPSCALE);
            long long q1 = __float2ll_rn((v.z * v.z + v.w * v.w) * FPSCALE);
            // 16 values/loc per slice: q-sum < 2^32, s in hi word exactly
            atomicAdd(&accP[loc],     (unsigned long long)((s0 << 32) + q0));
            atomicAdd(&accP[loc + 1], (unsigned long long)((s1 << 32) + q1));
        }
        __syncthreads();
        for (int e = tid; e < NLOC; e += 256)
            g_part[bid][e] = accP[e];           // plain write, slot owned
    } else if (bid == NPART) {
        // ---- W build (shuffle-U + A + wire contraction; R13 verbatim) ----
        {
            const int col = tid >> 4, K = tid & 15;
            float vr = (K == col) ? 1.f : 0.f, vi = 0.f;
            #pragma unroll
            for (int l = 0; l < 2; l++) {
                #pragma unroll
                for (int wi = 0; wi < 4; wi++) {   // RY(params[l][w][0])
                    float ss, cc; __sincosf(0.5f * params[(l * 4 + wi) * 3 + 0], &ss, &cc);
                    int m = 8 >> wi;
                    float orr = __shfl_xor_sync(0xffffffffu, vr, m);
                    float oii = __shfl_xor_sync(0xffffffffu, vi, m);
                    if (K & m) { vr = fmaf(ss, orr, cc * vr);  vi = fmaf(ss, oii, cc * vi); }
                    else       { vr = fmaf(-ss, orr, cc * vr); vi = fmaf(-ss, oii, cc * vi); }
                }
                #pragma unroll
                for (int i = 0; i < 3; i++) {      // CNOT(i -> i+1)
                    int cm = 8 >> i, tm = 8 >> (i + 1);
                    float orr = __shfl_xor_sync(0xffffffffu, vr, tm);
                    float oii = __shfl_xor_sync(0xffffffffu, vi, tm);
                    if (K & cm) { vr = orr; vi = oii; }
                }
                #pragma unroll
                for (int wi = 0; wi < 4; wi++) {   // RY(params[l][w][1])
                    float ss, cc; __sincosf(0.5f * params[(l * 4 + wi) * 3 + 1], &ss, &cc);
                    int m = 8 >> wi;
                    float orr = __shfl_xor_sync(0xffffffffu, vr, m);
                    float oii = __shfl_xor_sync(0xffffffffu, vi, m);
                    if (K & m) { vr = fmaf(ss, orr, cc * vr);  vi = fmaf(ss, oii, cc * vi); }
                    else       { vr = fmaf(-ss, orr, cc * vr); vi = fmaf(-ss, oii, cc * vi); }
                }
                #pragma unroll
                for (int i = 0; i < 3; i++) {      // CNOT(i+1 -> i)
                    int cm = 8 >> (i + 1), tm = 8 >> i;
                    float orr = __shfl_xor_sync(0xffffffffu, vr, tm);
                    float oii = __shfl_xor_sync(0xffffffffu, vi, tm);
                    if (K & cm) { vr = orr; vi = oii; }
                }
                #pragma unroll
                for (int wi = 0; wi < 4; wi++) {   // RZ(params[l][w][2])
                    float ss, cc; __sincosf(0.5f * params[(l * 4 + wi) * 3 + 2], &ss, &cc);
                    int m = 8 >> wi;
                    float rr = vr, ii = vi;
                    if (K & m) { vr = rr * cc - ii * ss; vi = ii * cc + rr * ss; }
                    else       { vr = rr * cc + ii * ss; vi = ii * cc - rr * ss; }
                }
            }
            sP[K * 17 + col] = vr;
            sQ[K * 17 + col] = vi;
        }
        __syncthreads();
        {
            const int k = tid >> 4, kp = tid & 15;
            float A0 = 0.f, A1 = 0.f, A2 = 0.f, A3 = 0.f;
            #pragma unroll
            for (int K = 0; K < 16; K++) {
                float pp = fmaf(sP[K * 17 + k], sP[K * 17 + kp],
                                sQ[K * 17 + k] * sQ[K * 17 + kp]);
                if (K & 8) A0 -= pp; else A0 += pp;
                if (K & 4) A1 -= pp; else A1 += pp;
                if (K & 2) A2 -= pp; else A2 += pp;
                if (K & 1) A3 -= pp; else A3 += pp;
            }
            int pi = 2 * spread4(k) + spread4(kp);
            bufA[0][pi] = A0; bufA[1][pi] = A1; bufA[2][pi] = A2; bufA[3][pi] = A3;
        }
        __syncthreads();
        CSTEP(bufA, bufB, 64, 1);
        CSTEP(bufB, bufA, 16, 3);
        CSTEP(bufA, bufB, 4, 9);
        CSTEP(bufB, bufA, 1, 27);
        if (tid < 81)
            g_W[tid] = make_float4(bufA[0][tid], bufA[1][tid], bufA[2][tid], bufA[3][tid]);
    }

    grid_barrier(0);

    // ================= Phase B: reduce partials -> g_stats =================
    {
        const int gw = bid * 8 + (tid >> 5);   // global warp id
        if (gw < NLOC) {
            const int lane = tid & 31;
            long long Sacc = 0, Qacc = 0;
            #pragma unroll
            for (int j = 0; j < 4; j++) {
                unsigned long long P = g_part[lane + 32 * j][gw];
                Sacc += (long long)(int)(P >> 32);
                Qacc += (long long)(P & 0xffffffffULL);
            }
            #pragma unroll
            for (int o = 16; o > 0; o >>= 1) {
                Sacc += __shfl_down_sync(0xffffffffu, Sacc, o);
                Qacc += __shfl_down_sync(0xffffffffu, Qacc, o);
            }
            if (lane == 0) {
                float S = (float)Sacc * INV_FPSCALE;
                float Q = (float)Qacc * INV_FPSCALE;
                float mean = S * (1.f / 2048.f);
                float ssd  = Q - S * S * (1.f / 2048.f);
                float sd   = sqrtf(ssd * (1.f / 2047.f));
                g_stats[gw] = make_float2(mean, __fdividef(PI_F, sd + 1e-8f));
            }
        }
    }

    grid_barrier(1);

    // ================= Phase C: eval (blocks 0-127, 4 batches each) =========
    if (bid >= NPART) return;

    for (int i = tid; i < 784; i += 256)
        reinterpret_cast<float4*>(sx)[i] = reinterpret_cast<const float4*>(x)[bid * 784 + i];
    if (tid < 81)  sWk[tid]  = g_W[tid];
    for (int e = tid; e < NLOC; e += 256) sStats[e] = g_stats[e];
    __syncthreads();

    #pragma unroll
    for (int it = 0; it < 4; it++) {
        int s = tid + it * 256;
        if (s >= 784) break;
        int bb  = s / 196;
        int loc = s - bb * 196;
        int r = loc / 14, c = loc - r * 14;

        float2 st = sStats[loc];
        float2 u  = *reinterpret_cast<float2*>(&sx[bb * 784 + (2 * r) * 28 + 2 * c]);
        float2 w2 = *reinterpret_cast<float2*>(&sx[bb * 784 + (2 * r + 1) * 28 + 2 * c]);

        float C0, S0, C1, S1, C2, S2, C3, S3;
        __sincosf((u.x  - st.x) * st.y, &S0, &C0);
        __sincosf((u.y  - st.x) * st.y, &S1, &C1);
        __sincosf((w2.x - st.x) * st.y, &S2, &C2);
        __sincosf((w2.y - st.x) * st.y, &S3, &C3);

        float v01[9], v23[9];
        v01[0] = 1.f; v01[1] = C1;      v01[2] = S1;
        v01[3] = C0;  v01[4] = C0 * C1; v01[5] = C0 * S1;
        v01[6] = S0;  v01[7] = S0 * C1; v01[8] = S0 * S1;
        v23[0] = 1.f; v23[1] = C3;      v23[2] = S3;
        v23[3] = C2;  v23[4] = C2 * C3; v23[5] = C2 * S3;
        v23[6] = S2;  v23[7] = S2 * C3; v23[8] = S2 * S3;

        float z0 = 0.f, z1 = 0.f, z2 = 0.f, z3 = 0.f;
        #pragma unroll
        for (int al = 0; al < 9; al++) {
            float t0 = 0.f, t1 = 0.f, t2 = 0.f, t3 = 0.f;
            #pragma unroll
            for (int be = 0; be < 9; be++) {
                float4 wv = sWk[al * 9 + be];    // LDS.128 broadcast
                float vb = v23[be];
                t0 = fmaf(wv.x, vb, t0); t1 = fmaf(wv.y, vb, t1);
                t2 = fmaf(wv.z, vb, t2); t3 = fmaf(wv.w, vb, t3);
            }
            float ca = v01[al];
            z0 = fmaf(ca, t0, z0); z1 = fmaf(ca, t1, z1);
            z2 = fmaf(ca, t2, z2); z3 = fmaf(ca, t3, z3);
        }

        // out4[bid*784 + s] — contiguous per block, coalesced STG.128
        reinterpret_cast<float4*>(out)[bid * 784 + s] = make_float4(z0, z1, z2, z3);
    }
}

extern "C" void kernel_launch(void* const* d_in, const int* in_sizes, int n_in,
                              void* d_out, int out_size) {
    const float* x      = (const float*)d_in[0];   // (512, 28, 28)
    const float* params = (const float*)d_in[1];   // (2, 4, 3)
    float* out          = (float*)d_out;           // (512, 784)

    qf_persistent<<<NBLK, 256>>>(x, params, out);
}